// round 13
// baseline (speedup 1.0000x reference)
#include <cuda_runtime.h>
#include <cuda_fp16.h>
#include <cstdint>
typedef unsigned int u32;

#define NTH  512
#define BT   64
// smem byte offsets
#define SO_BH   0          // B fp16 frags [16q][32lane][16u32]   32768
#define SO_BIAS 32768      // 9*256 fp32                           9216
#define SO_WRO  41984      // 10*256 fp32                         10240
#define SO_BRO  52224      // 10 fp32 (pad 64)                       64
#define SO_DW   52288      // 8*64 fp32                            2048
#define SO_RED  54336      // 16*64 fp32                           4096
#define SM_TOT  58432

// A fragments (fp16): [chunk 0..143 (+2 pad)][split hi/lo][mtile 16][lane 32][4 u32]
__device__ __align__(256) u32 g_A[146 * 4096];

__device__ __forceinline__ u32 pkhf(float a, float b) {
    __half2 h = __floats2half2_rn(a, b);
    return *(u32*)&h;
}
__device__ __forceinline__ void mma16816(float c[4], const uint4& a, u32 b0, u32 b1) {
    asm volatile("mma.sync.aligned.m16n8k16.row.col.f32.f16.f16.f32 "
        "{%0,%1,%2,%3}, {%4,%5,%6,%7}, {%8,%9}, {%0,%1,%2,%3};"
        : "+f"(c[0]), "+f"(c[1]), "+f"(c[2]), "+f"(c[3])
        : "r"(a.x), "r"(a.y), "r"(a.z), "r"(a.w), "r"(b0), "r"(b1));
}

// ---------------- prep: rho-fold + fp16 hi/lo split + fragment layout -------
__global__ void prep_kernel(const float* __restrict__ B1m, const float* __restrict__ B2m,
                            const float* __restrict__ r1, const float* __restrict__ r3) {
    int idx = blockIdx.x * 256 + threadIdx.x;
    if (idx >= 144 * 16 * 32 * 4) return;
    int r = idx & 3, l = (idx >> 2) & 31, mt = (idx >> 7) & 15, ch = idx >> 11;
    int m = ch >> 4, q = ch & 15;
    int gg = l >> 2, tt = l & 3;
    int i = mt * 16 + gg + ((r & 1) ? 8 : 0);
    int k = q * 16 + 2 * tt + ((r & 2) ? 8 : 0);
    float rho = (m == 0) ? r1[0] : r3[0];
    const float* Bs = (m == 0) ? (B1m + i * 256) : (B2m + (m - 1) * 65536 + i * 256);
    float v0 = rho * Bs[k], v1 = rho * Bs[k + 1];
    __half h0 = __float2half_rn(v0), h1 = __float2half_rn(v1);
    float e0 = v0 - __half2float(h0), e1 = v1 - __half2float(h1);
    int base = ch * 4096 + mt * 128 + l * 4 + r;
    g_A[base]        = ((u32)__half_as_ushort(h0)) | ((u32)__half_as_ushort(h1) << 16);
    g_A[base + 2048] = pkhf(e0, e1);
}

// ---------------- main kernel ------------------------------------------------
__global__ __launch_bounds__(NTH, 1)
void sde_kernel(const float* __restrict__ V, const float* __restrict__ inc,
                const float* __restrict__ W1, const float* __restrict__ b1v,
                const float* __restrict__ W2, const float* __restrict__ b2v,
                const float* __restrict__ rho2, const float* __restrict__ rho4,
                const float* __restrict__ lam1, const float* __restrict__ lam2,
                const float* __restrict__ Wro,  const float* __restrict__ bro,
                float* __restrict__ out) {
    extern __shared__ __align__(16) char sm[];
    u32*   BH    = (u32*)(sm + SO_BH);
    float* biasS = (float*)(sm + SO_BIAS);
    float* WroS  = (float*)(sm + SO_WRO);
    float* broS  = (float*)(sm + SO_BRO);
    float* dWs   = (float*)(sm + SO_DW);
    float* red   = (float*)(sm + SO_RED);

    const int tid = threadIdx.x, lane = tid & 31, w = tid >> 5;
    const int g = lane >> 2, t = lane & 3;
    const int bBase = blockIdx.x * BT;
    const int iLo = w * 16 + g, iHi = iLo + 8;

    // prologue: biases (rho folded), readout weights
    {
        float r2 = rho2[0], r4 = rho4[0];
        for (int e = tid; e < 2304; e += NTH) {
            int m = e >> 8, i = e & 255;
            biasS[e] = (m == 0) ? r2 * lam1[i] : r4 * lam2[(m - 1) * 256 + i];
        }
        for (int e = tid; e < 2560; e += NTH) WroS[e] = Wro[e];
        if (tid < 10) broS[tid] = bro[tid];
    }
    // hT[j][b] = tanh(V W1^T + b1), staged in BH region
    float* hT = (float*)(sm + SO_BH);
    for (int e = tid; e < 2048; e += NTH) {
        int j = e & 31, b = e >> 5;
        const float* vb = V + (size_t)(bBase + b) * 16;
        const float* ww = W1 + j * 16;
        float s = b1v[j];
#pragma unroll
        for (int u = 0; u < 16; u++) s += vb[u] * ww[u];
        hT[j * 64 + b] = tanhf(s);
    }
    __syncthreads();

    // R0 in regs: R[n][{(iLo,cLo),(iLo,cHi),(iHi,cLo),(iHi,cHi)}], cLo=n*8+2t
    float R[8][4];
#pragma unroll
    for (int n = 0; n < 8; n++) R[n][0] = R[n][1] = R[n][2] = R[n][3] = 0.f;
    for (int j = 0; j < 32; j++) {
        float w2l = W2[iLo * 32 + j], w2h = W2[iHi * 32 + j];
#pragma unroll
        for (int n = 0; n < 8; n++) {
            float2 hv = *(const float2*)&hT[j * 64 + n * 8 + 2 * t];
            R[n][0] += hv.x * w2l; R[n][1] += hv.y * w2l;
            R[n][2] += hv.x * w2h; R[n][3] += hv.y * w2h;
        }
    }
    {
        float b2l = b2v[iLo], b2h = b2v[iHi];
#pragma unroll
        for (int n = 0; n < 8; n++) {
            R[n][0] += b2l; R[n][1] += b2l; R[n][2] += b2h; R[n][3] += b2h;
        }
    }
    __syncthreads();                 // hT region free (becomes BH)

    auto readout = [&](int ts) {
        float wl = WroS[ts * 256 + iLo], wh = WroS[ts * 256 + iHi];
        float pc[16];
#pragma unroll
        for (int n = 0; n < 8; n++) {
            pc[2 * n]     = R[n][0] * wl + R[n][2] * wh;
            pc[2 * n + 1] = R[n][1] * wl + R[n][3] * wh;
        }
#pragma unroll
        for (int k = 0; k < 16; k++) {
            pc[k] += __shfl_xor_sync(0xFFFFFFFFu, pc[k], 4);
            pc[k] += __shfl_xor_sync(0xFFFFFFFFu, pc[k], 8);
            pc[k] += __shfl_xor_sync(0xFFFFFFFFu, pc[k], 16);
        }
        if (lane < 4) {
#pragma unroll
            for (int n = 0; n < 8; n++) {
                red[w * 64 + n * 8 + 2 * lane]     = pc[2 * n];
                red[w * 64 + n * 8 + 2 * lane + 1] = pc[2 * n + 1];
            }
        }
        __syncthreads();
        if (tid < 64) {
            float a = broS[ts];
#pragma unroll
            for (int ww = 0; ww < 16; ww++) a += red[ww * 64 + tid];
            out[(size_t)(bBase + tid) * 10 + ts] = a;
        }
    };

    // pack fp16 B fragments from fp32 R: layout [q=w][lane][16 u32]
    auto writeB = [&]() {
        u32 vA[16], vB[16];
#pragma unroll
        for (int n = 0; n < 8; n++) {
            u32 Ph01 = pkhf(R[n][0], R[n][1]);
            u32 Ph23 = pkhf(R[n][2], R[n][3]);
            u32 Rh01 = __shfl_xor_sync(0xFFFFFFFFu, Ph01, 4);
            u32 Rh23 = __shfl_xor_sync(0xFFFFFFFFu, Ph23, 4);
            vA[2 * n]     = __byte_perm(Ph01, Rh01, 0x5410);
            vA[2 * n + 1] = __byte_perm(Ph23, Rh23, 0x5410);
            vB[2 * n]     = __byte_perm(Ph01, Rh01, 0x7632);
            vB[2 * n + 1] = __byte_perm(Ph23, Rh23, 0x7632);
        }
        if ((g & 1) == 0) {
            int a  = g >> 1;
            int lA = 8 * t + a, lB = lA + 4;
            uint4* pA = (uint4*)(BH + w * 512 + lA * 16);
            uint4* pB = (uint4*)(BH + w * 512 + lB * 16);
#pragma unroll
            for (int u = 0; u < 4; u++) {
                pA[u] = make_uint4(vA[4*u], vA[4*u+1], vA[4*u+2], vA[4*u+3]);
                pB[u] = make_uint4(vB[4*u], vB[4*u+1], vB[4*u+2], vB[4*u+3]);
            }
        }
    };

    readout(0);
    __syncthreads();
    writeB();

    const uint4* gA4 = (const uint4*)g_A;
    const int aoff = w * 32 + lane;
    const uint4* BH4 = (const uint4*)BH;   // q*128 + lane*4

    float acc[8][4];
#pragma unroll
    for (int n = 0; n < 8; n++) acc[n][0] = acc[n][1] = acc[n][2] = acc[n][3] = 0.f;

    auto domma = [&](const uint4& ah, const uint4& al,
                     const uint4& b0, const uint4& b1,
                     const uint4& b2, const uint4& b3) {
        mma16816(acc[0], ah, b0.x, b0.y); mma16816(acc[1], ah, b0.z, b0.w);
        mma16816(acc[2], ah, b1.x, b1.y); mma16816(acc[3], ah, b1.z, b1.w);
        mma16816(acc[4], ah, b2.x, b2.y); mma16816(acc[5], ah, b2.z, b2.w);
        mma16816(acc[6], ah, b3.x, b3.y); mma16816(acc[7], ah, b3.z, b3.w);
        mma16816(acc[0], al, b0.x, b0.y); mma16816(acc[1], al, b0.z, b0.w);
        mma16816(acc[2], al, b1.x, b1.y); mma16816(acc[3], al, b1.z, b1.w);
        mma16816(acc[4], al, b2.x, b2.y); mma16816(acc[5], al, b2.z, b2.w);
        mma16816(acc[6], al, b3.x, b3.y); mma16816(acc[7], al, b3.z, b3.w);
    };
    auto epi = [&](int m) {
        float bLo = biasS[m * 256 + iLo], bHi = biasS[m * 256 + iHi];
        if (m == 0) {
#pragma unroll
            for (int n = 0; n < 8; n++) {
                R[n][0] += tanhf(acc[n][0] + bLo);
                R[n][1] += tanhf(acc[n][1] + bLo);
                R[n][2] += tanhf(acc[n][2] + bHi);
                R[n][3] += tanhf(acc[n][3] + bHi);
                acc[n][0] = acc[n][1] = acc[n][2] = acc[n][3] = 0.f;
            }
        } else {
#pragma unroll
            for (int n = 0; n < 8; n++) {
                float2 dw = *(const float2*)&dWs[(m - 1) * 64 + n * 8 + 2 * t];
                R[n][0] += tanhf(acc[n][0] + bLo) * dw.x;
                R[n][1] += tanhf(acc[n][1] + bLo) * dw.y;
                R[n][2] += tanhf(acc[n][2] + bHi) * dw.x;
                R[n][3] += tanhf(acc[n][3] + bHi) * dw.y;
                acc[n][0] = acc[n][1] = acc[n][2] = acc[n][3] = 0.f;
            }
        }
    };

    for (int s = 0; s < 9; s++) {
        {   // dW for this step
            int m = tid >> 6, b = tid & 63;
            const float* ib = inc + (size_t)(bBase + b) * 80;
            dWs[tid] = (s == 0) ? (ib[m] + ib[8 + m]) : ib[(s + 1) * 8 + m];
        }
        __syncthreads();            // dW + B frags visible to all

        const uint4* pab = gA4 + aoff;
        const uint4* bl0 = BH4 + lane * 4;   // q=0
        uint4 a0h = pab[0], a0l = pab[512];
        uint4 c0 = bl0[0], c1 = bl0[1], c2 = bl0[2], c3 = bl0[3];

#pragma unroll 1
        for (int ch = 0; ch < 144; ch += 2) {
            // prefetch chunk ch+1 (A + B frags)
            uint4 a1h = pab[1024], a1l = pab[1536];
            const uint4* bq1 = BH4 + (((ch + 1) & 15) * 128 + lane * 4);
            uint4 d0 = bq1[0], d1 = bq1[1], d2 = bq1[2], d3 = bq1[3];
            domma(a0h, a0l, c0, c1, c2, c3);
            // prefetch chunk ch+2 (pad chunks make this always safe)
            a0h = pab[2048]; a0l = pab[2560];
            const uint4* bq2 = BH4 + (((ch + 2) & 15) * 128 + lane * 4);
            c0 = bq2[0]; c1 = bq2[1]; c2 = bq2[2]; c3 = bq2[3];
            domma(a1h, a1l, d0, d1, d2, d3);
            if (((ch + 1) & 15) == 15) epi((ch + 1) >> 4);
            pab += 2048;
        }

        readout(s + 1);
        __syncthreads();            // all B-frag reads + red reads done
        if (s < 8) writeB();
    }
}

// ---------------- launch -----------------------------------------------------
extern "C" void kernel_launch(void* const* d_in, const int* in_sizes, int n_in,
                              void* d_out, int out_size) {
    const float* V    = (const float*)d_in[0];
    const float* inc  = (const float*)d_in[1];
    const float* W1   = (const float*)d_in[2];
    const float* b1v  = (const float*)d_in[3];
    const float* W2   = (const float*)d_in[4];
    const float* b2v  = (const float*)d_in[5];
    const float* rho1 = (const float*)d_in[6];
    const float* rho2 = (const float*)d_in[7];
    const float* rho3 = (const float*)d_in[8];
    const float* rho4 = (const float*)d_in[9];
    const float* B1m  = (const float*)d_in[10];
    const float* B2m  = (const float*)d_in[11];
    const float* lam1 = (const float*)d_in[12];
    const float* lam2 = (const float*)d_in[13];
    const float* Wro  = (const float*)d_in[14];
    const float* bro  = (const float*)d_in[15];
    float* out = (float*)d_out;

    const int nB = in_sizes[0] / 16;                  // 16384
    prep_kernel<<<(144 * 16 * 32 * 4 + 255) / 256, 256>>>(B1m, B2m, rho1, rho3);

    cudaFuncSetAttribute(sde_kernel, cudaFuncAttributeMaxDynamicSharedMemorySize, SM_TOT);
    sde_kernel<<<nB / BT, NTH, SM_TOT>>>(V, inc, W1, b1v, W2, b2v,
                                         rho2, rho4, lam1, lam2, Wro, bro, out);
}

// round 14
// speedup vs baseline: 1.7402x; 1.7402x over previous
#include <cuda_runtime.h>
#include <cuda_fp16.h>
#include <cstdint>
typedef unsigned int u32;

#define NTH  512
#define BT   64
// smem byte offsets
#define SO_BH   0          // B fp16 frags [16q][4u][32lane][4u32] 32768
#define SO_BIAS 32768      // 9*256 fp32                           9216
#define SO_WRO  41984      // 10*256 fp32                         10240
#define SO_BRO  52224      // 10 fp32 (pad 64)                       64
#define SO_DW   52288      // 8*64 fp32                            2048
#define SO_RED  54336      // 16*64 fp32                           4096
#define SM_TOT  58432

// A fragments (fp16): [chunk 0..143 (+2 pad)][split hi/lo][mtile 16][lane 32][4 u32]
__device__ __align__(256) u32 g_A[146 * 4096];

__device__ __forceinline__ u32 pkhf(float a, float b) {
    __half2 h = __floats2half2_rn(a, b);
    return *(u32*)&h;
}
__device__ __forceinline__ void mma16816(float c[4], const uint4& a, u32 b0, u32 b1) {
    asm volatile("mma.sync.aligned.m16n8k16.row.col.f32.f16.f16.f32 "
        "{%0,%1,%2,%3}, {%4,%5,%6,%7}, {%8,%9}, {%0,%1,%2,%3};"
        : "+f"(c[0]), "+f"(c[1]), "+f"(c[2]), "+f"(c[3])
        : "r"(a.x), "r"(a.y), "r"(a.z), "r"(a.w), "r"(b0), "r"(b1));
}

// ---------------- prep: rho-fold + fp16 hi/lo split + fragment layout -------
__global__ void prep_kernel(const float* __restrict__ B1m, const float* __restrict__ B2m,
                            const float* __restrict__ r1, const float* __restrict__ r3) {
    int idx = blockIdx.x * 256 + threadIdx.x;
    if (idx >= 144 * 16 * 32 * 4) return;
    int r = idx & 3, l = (idx >> 2) & 31, mt = (idx >> 7) & 15, ch = idx >> 11;
    int m = ch >> 4, q = ch & 15;
    int gg = l >> 2, tt = l & 3;
    int i = mt * 16 + gg + ((r & 1) ? 8 : 0);
    int k = q * 16 + 2 * tt + ((r & 2) ? 8 : 0);
    float rho = (m == 0) ? r1[0] : r3[0];
    const float* Bs = (m == 0) ? (B1m + i * 256) : (B2m + (m - 1) * 65536 + i * 256);
    float v0 = rho * Bs[k], v1 = rho * Bs[k + 1];
    __half h0 = __float2half_rn(v0), h1 = __float2half_rn(v1);
    float e0 = v0 - __half2float(h0), e1 = v1 - __half2float(h1);
    int base = ch * 4096 + mt * 128 + l * 4 + r;
    g_A[base]        = ((u32)__half_as_ushort(h0)) | ((u32)__half_as_ushort(h1) << 16);
    g_A[base + 2048] = pkhf(e0, e1);
}

// ---------------- main kernel ------------------------------------------------
__global__ __launch_bounds__(NTH, 1)
void sde_kernel(const float* __restrict__ V, const float* __restrict__ inc,
                const float* __restrict__ W1, const float* __restrict__ b1v,
                const float* __restrict__ W2, const float* __restrict__ b2v,
                const float* __restrict__ rho2, const float* __restrict__ rho4,
                const float* __restrict__ lam1, const float* __restrict__ lam2,
                const float* __restrict__ Wro,  const float* __restrict__ bro,
                float* __restrict__ out) {
    extern __shared__ __align__(16) char sm[];
    u32*   BH    = (u32*)(sm + SO_BH);
    float* biasS = (float*)(sm + SO_BIAS);
    float* WroS  = (float*)(sm + SO_WRO);
    float* broS  = (float*)(sm + SO_BRO);
    float* dWs   = (float*)(sm + SO_DW);
    float* red   = (float*)(sm + SO_RED);

    const int tid = threadIdx.x, lane = tid & 31, w = tid >> 5;
    const int g = lane >> 2, t = lane & 3;
    const int bBase = blockIdx.x * BT;
    const int iLo = w * 16 + g, iHi = iLo + 8;

    // prologue: biases (rho folded), readout weights
    {
        float r2 = rho2[0], r4 = rho4[0];
        for (int e = tid; e < 2304; e += NTH) {
            int m = e >> 8, i = e & 255;
            biasS[e] = (m == 0) ? r2 * lam1[i] : r4 * lam2[(m - 1) * 256 + i];
        }
        for (int e = tid; e < 2560; e += NTH) WroS[e] = Wro[e];
        if (tid < 10) broS[tid] = bro[tid];
    }
    // hT[j][b] = tanh(V W1^T + b1), staged in BH region
    float* hT = (float*)(sm + SO_BH);
    for (int e = tid; e < 2048; e += NTH) {
        int j = e & 31, b = e >> 5;
        const float* vb = V + (size_t)(bBase + b) * 16;
        const float* ww = W1 + j * 16;
        float s = b1v[j];
#pragma unroll
        for (int u = 0; u < 16; u++) s += vb[u] * ww[u];
        hT[j * 64 + b] = tanhf(s);
    }
    __syncthreads();

    // R0 in regs: R[n][{(iLo,cLo),(iLo,cHi),(iHi,cLo),(iHi,cHi)}], cLo=n*8+2t
    float R[8][4];
#pragma unroll
    for (int n = 0; n < 8; n++) R[n][0] = R[n][1] = R[n][2] = R[n][3] = 0.f;
    for (int j = 0; j < 32; j++) {
        float w2l = W2[iLo * 32 + j], w2h = W2[iHi * 32 + j];
#pragma unroll
        for (int n = 0; n < 8; n++) {
            float2 hv = *(const float2*)&hT[j * 64 + n * 8 + 2 * t];
            R[n][0] += hv.x * w2l; R[n][1] += hv.y * w2l;
            R[n][2] += hv.x * w2h; R[n][3] += hv.y * w2h;
        }
    }
    {
        float b2l = b2v[iLo], b2h = b2v[iHi];
#pragma unroll
        for (int n = 0; n < 8; n++) {
            R[n][0] += b2l; R[n][1] += b2l; R[n][2] += b2h; R[n][3] += b2h;
        }
    }
    __syncthreads();                 // hT region free (becomes BH)

    auto readout = [&](int ts) {
        float wl = WroS[ts * 256 + iLo], wh = WroS[ts * 256 + iHi];
        float pc[16];
#pragma unroll
        for (int n = 0; n < 8; n++) {
            pc[2 * n]     = R[n][0] * wl + R[n][2] * wh;
            pc[2 * n + 1] = R[n][1] * wl + R[n][3] * wh;
        }
#pragma unroll
        for (int k = 0; k < 16; k++) {
            pc[k] += __shfl_xor_sync(0xFFFFFFFFu, pc[k], 4);
            pc[k] += __shfl_xor_sync(0xFFFFFFFFu, pc[k], 8);
            pc[k] += __shfl_xor_sync(0xFFFFFFFFu, pc[k], 16);
        }
        if (lane < 4) {
#pragma unroll
            for (int n = 0; n < 8; n++) {
                red[w * 64 + n * 8 + 2 * lane]     = pc[2 * n];
                red[w * 64 + n * 8 + 2 * lane + 1] = pc[2 * n + 1];
            }
        }
        __syncthreads();
        if (tid < 64) {
            float a = broS[ts];
#pragma unroll
            for (int ww = 0; ww < 16; ww++) a += red[ww * 64 + tid];
            out[(size_t)(bBase + tid) * 10 + ts] = a;
        }
    };

    // pack fp16 B fragments from fp32 R: layout [q=w][u:4][lane:32][4 u32]
    auto writeB = [&]() {
        u32 vA[16], vB[16];
#pragma unroll
        for (int n = 0; n < 8; n++) {
            u32 Ph01 = pkhf(R[n][0], R[n][1]);
            u32 Ph23 = pkhf(R[n][2], R[n][3]);
            u32 Rh01 = __shfl_xor_sync(0xFFFFFFFFu, Ph01, 4);
            u32 Rh23 = __shfl_xor_sync(0xFFFFFFFFu, Ph23, 4);
            vA[2 * n]     = __byte_perm(Ph01, Rh01, 0x5410);
            vA[2 * n + 1] = __byte_perm(Ph23, Rh23, 0x5410);
            vB[2 * n]     = __byte_perm(Ph01, Rh01, 0x7632);
            vB[2 * n + 1] = __byte_perm(Ph23, Rh23, 0x7632);
        }
        if ((g & 1) == 0) {
            int a  = g >> 1;
            int lA = 8 * t + a, lB = lA + 4;
            uint4* base = (uint4*)(BH + w * 512);
#pragma unroll
            for (int u = 0; u < 4; u++) {
                base[u * 32 + lA] = make_uint4(vA[4*u], vA[4*u+1], vA[4*u+2], vA[4*u+3]);
                base[u * 32 + lB] = make_uint4(vB[4*u], vB[4*u+1], vB[4*u+2], vB[4*u+3]);
            }
        }
    };

    readout(0);
    __syncthreads();
    writeB();

    const uint4* gA4 = (const uint4*)g_A;
    const int aoff = w * 32 + lane;
    const uint4* BH4 = (const uint4*)BH;   // q*128 + u*32 + lane

    float acc[8][4];
#pragma unroll
    for (int n = 0; n < 8; n++) acc[n][0] = acc[n][1] = acc[n][2] = acc[n][3] = 0.f;

    auto domma = [&](const uint4& ah, const uint4& al,
                     const uint4& b0, const uint4& b1,
                     const uint4& b2, const uint4& b3) {
        mma16816(acc[0], ah, b0.x, b0.y); mma16816(acc[1], ah, b0.z, b0.w);
        mma16816(acc[2], ah, b1.x, b1.y); mma16816(acc[3], ah, b1.z, b1.w);
        mma16816(acc[4], ah, b2.x, b2.y); mma16816(acc[5], ah, b2.z, b2.w);
        mma16816(acc[6], ah, b3.x, b3.y); mma16816(acc[7], ah, b3.z, b3.w);
        mma16816(acc[0], al, b0.x, b0.y); mma16816(acc[1], al, b0.z, b0.w);
        mma16816(acc[2], al, b1.x, b1.y); mma16816(acc[3], al, b1.z, b1.w);
        mma16816(acc[4], al, b2.x, b2.y); mma16816(acc[5], al, b2.z, b2.w);
        mma16816(acc[6], al, b3.x, b3.y); mma16816(acc[7], al, b3.z, b3.w);
    };
    auto epi = [&](int m) {
        float bLo = biasS[m * 256 + iLo], bHi = biasS[m * 256 + iHi];
        if (m == 0) {
#pragma unroll
            for (int n = 0; n < 8; n++) {
                R[n][0] += tanhf(acc[n][0] + bLo);
                R[n][1] += tanhf(acc[n][1] + bLo);
                R[n][2] += tanhf(acc[n][2] + bHi);
                R[n][3] += tanhf(acc[n][3] + bHi);
                acc[n][0] = acc[n][1] = acc[n][2] = acc[n][3] = 0.f;
            }
        } else {
#pragma unroll
            for (int n = 0; n < 8; n++) {
                float2 dw = *(const float2*)&dWs[(m - 1) * 64 + n * 8 + 2 * t];
                R[n][0] += tanhf(acc[n][0] + bLo) * dw.x;
                R[n][1] += tanhf(acc[n][1] + bLo) * dw.y;
                R[n][2] += tanhf(acc[n][2] + bHi) * dw.x;
                R[n][3] += tanhf(acc[n][3] + bHi) * dw.y;
                acc[n][0] = acc[n][1] = acc[n][2] = acc[n][3] = 0.f;
            }
        }
    };

    for (int s = 0; s < 9; s++) {
        {   // dW for this step
            int m = tid >> 6, b = tid & 63;
            const float* ib = inc + (size_t)(bBase + b) * 80;
            dWs[tid] = (s == 0) ? (ib[m] + ib[8 + m]) : ib[(s + 1) * 8 + m];
        }
        __syncthreads();            // dW + B frags visible to all

        const uint4* pab = gA4 + aoff;
        const uint4* bl0 = BH4 + lane;       // q=0
        uint4 a0h = pab[0], a0l = pab[512];
        uint4 c0 = bl0[0], c1 = bl0[32], c2 = bl0[64], c3 = bl0[96];

#pragma unroll 1
        for (int ch = 0; ch < 144; ch += 2) {
            // prefetch chunk ch+1 (A + B frags)
            uint4 a1h = pab[1024], a1l = pab[1536];
            const uint4* bq1 = BH4 + (((ch + 1) & 15) * 128 + lane);
            uint4 d0 = bq1[0], d1 = bq1[32], d2 = bq1[64], d3 = bq1[96];
            domma(a0h, a0l, c0, c1, c2, c3);
            // prefetch chunk ch+2 (pad chunks make this always safe)
            a0h = pab[2048]; a0l = pab[2560];
            const uint4* bq2 = BH4 + (((ch + 2) & 15) * 128 + lane);
            c0 = bq2[0]; c1 = bq2[32]; c2 = bq2[64]; c3 = bq2[96];
            domma(a1h, a1l, d0, d1, d2, d3);
            if (((ch + 1) & 15) == 15) epi((ch + 1) >> 4);
            pab += 2048;
        }

        readout(s + 1);
        __syncthreads();            // all B-frag reads + red reads done
        if (s < 8) writeB();
    }
}

// ---------------- launch -----------------------------------------------------
extern "C" void kernel_launch(void* const* d_in, const int* in_sizes, int n_in,
                              void* d_out, int out_size) {
    const float* V    = (const float*)d_in[0];
    const float* inc  = (const float*)d_in[1];
    const float* W1   = (const float*)d_in[2];
    const float* b1v  = (const float*)d_in[3];
    const float* W2   = (const float*)d_in[4];
    const float* b2v  = (const float*)d_in[5];
    const float* rho1 = (const float*)d_in[6];
    const float* rho2 = (const float*)d_in[7];
    const float* rho3 = (const float*)d_in[8];
    const float* rho4 = (const float*)d_in[9];
    const float* B1m  = (const float*)d_in[10];
    const float* B2m  = (const float*)d_in[11];
    const float* lam1 = (const float*)d_in[12];
    const float* lam2 = (const float*)d_in[13];
    const float* Wro  = (const float*)d_in[14];
    const float* bro  = (const float*)d_in[15];
    float* out = (float*)d_out;

    const int nB = in_sizes[0] / 16;                  // 16384
    prep_kernel<<<(144 * 16 * 32 * 4 + 255) / 256, 256>>>(B1m, B2m, rho1, rho3);

    cudaFuncSetAttribute(sde_kernel, cudaFuncAttributeMaxDynamicSharedMemorySize, SM_TOT);
    sde_kernel<<<nB / BT, NTH, SM_TOT>>>(V, inc, W1, b1v, W2, b2v,
                                         rho2, rho4, lam1, lam2, Wro, bro, out);
}

// round 15
// speedup vs baseline: 2.4771x; 1.4235x over previous
#include <cuda_runtime.h>
#include <cuda_fp16.h>
#include <cstdint>
typedef unsigned int u32;

#define NTH  512
#define BT   64
// smem byte offsets
#define SO_BH   0          // B fp16 frags [16q][4u][32lane][4u32] 32768
#define SO_BIAS 32768      // 9*256 fp32                           9216
#define SO_WRO  41984      // 10*256 fp32                         10240
#define SO_BRO  52224      // 10 fp32 (pad 64)                       64
#define SO_DW   52288      // 8*64 fp32                            2048
#define SO_RED  54336      // 16*64 fp32                           4096
#define SM_TOT  58432

// A fragments (fp16 single precision-pass): [chunk 0..143 (+2 pad)][mtile 16][lane 32][4 u32]
__device__ __align__(256) u32 g_A[146 * 2048];

__device__ __forceinline__ u32 pkhf(float a, float b) {
    __half2 h = __floats2half2_rn(a, b);
    return *(u32*)&h;
}
// accurate fast tanh: (e^2x - 1)/(e^2x + 1), err ~2^-20, 5 instr / 2 MUFU
__device__ __forceinline__ float ftanh(float x) {
    float e;
    asm("ex2.approx.f32 %0, %1;" : "=f"(e) : "f"(x * 2.885390082f)); // exp(2x)
    float r;
    asm("rcp.approx.f32 %0, %1;" : "=f"(r) : "f"(e + 1.0f));
    return 1.0f - 2.0f * r;
}
__device__ __forceinline__ void mma16816(float c[4], const uint4& a, u32 b0, u32 b1) {
    asm volatile("mma.sync.aligned.m16n8k16.row.col.f32.f16.f16.f32 "
        "{%0,%1,%2,%3}, {%4,%5,%6,%7}, {%8,%9}, {%0,%1,%2,%3};"
        : "+f"(c[0]), "+f"(c[1]), "+f"(c[2]), "+f"(c[3])
        : "r"(a.x), "r"(a.y), "r"(a.z), "r"(a.w), "r"(b0), "r"(b1));
}

// ---------------- prep: rho-fold + fp16 + fragment layout -------------------
__global__ void prep_kernel(const float* __restrict__ B1m, const float* __restrict__ B2m,
                            const float* __restrict__ r1, const float* __restrict__ r3) {
    int idx = blockIdx.x * 256 + threadIdx.x;
    if (idx >= 144 * 16 * 32 * 4) return;
    int r = idx & 3, l = (idx >> 2) & 31, mt = (idx >> 7) & 15, ch = idx >> 11;
    int m = ch >> 4, q = ch & 15;
    int gg = l >> 2, tt = l & 3;
    int i = mt * 16 + gg + ((r & 1) ? 8 : 0);
    int k = q * 16 + 2 * tt + ((r & 2) ? 8 : 0);
    float rho = (m == 0) ? r1[0] : r3[0];
    const float* Bs = (m == 0) ? (B1m + i * 256) : (B2m + (m - 1) * 65536 + i * 256);
    g_A[ch * 2048 + mt * 128 + l * 4 + r] = pkhf(rho * Bs[k], rho * Bs[k + 1]);
}

// ---------------- main kernel ------------------------------------------------
__global__ __launch_bounds__(NTH, 1)
void sde_kernel(const float* __restrict__ V, const float* __restrict__ inc,
                const float* __restrict__ W1, const float* __restrict__ b1v,
                const float* __restrict__ W2, const float* __restrict__ b2v,
                const float* __restrict__ rho2, const float* __restrict__ rho4,
                const float* __restrict__ lam1, const float* __restrict__ lam2,
                const float* __restrict__ Wro,  const float* __restrict__ bro,
                float* __restrict__ out) {
    extern __shared__ __align__(16) char sm[];
    u32*   BH    = (u32*)(sm + SO_BH);
    float* biasS = (float*)(sm + SO_BIAS);
    float* WroS  = (float*)(sm + SO_WRO);
    float* broS  = (float*)(sm + SO_BRO);
    float* dWs   = (float*)(sm + SO_DW);
    float* red   = (float*)(sm + SO_RED);

    const int tid = threadIdx.x, lane = tid & 31, w = tid >> 5;
    const int g = lane >> 2, t = lane & 3;
    const int bBase = blockIdx.x * BT;
    const int iLo = w * 16 + g, iHi = iLo + 8;

    // prologue: biases (rho folded), readout weights
    {
        float r2 = rho2[0], r4 = rho4[0];
        for (int e = tid; e < 2304; e += NTH) {
            int m = e >> 8, i = e & 255;
            biasS[e] = (m == 0) ? r2 * lam1[i] : r4 * lam2[(m - 1) * 256 + i];
        }
        for (int e = tid; e < 2560; e += NTH) WroS[e] = Wro[e];
        if (tid < 10) broS[tid] = bro[tid];
    }
    // hT[j][b] = tanh(V W1^T + b1), staged in BH region
    float* hT = (float*)(sm + SO_BH);
    for (int e = tid; e < 2048; e += NTH) {
        int j = e & 31, b = e >> 5;
        const float* vb = V + (size_t)(bBase + b) * 16;
        const float* ww = W1 + j * 16;
        float s = b1v[j];
#pragma unroll
        for (int u = 0; u < 16; u++) s += vb[u] * ww[u];
        hT[j * 64 + b] = ftanh(s);
    }
    __syncthreads();

    // R0 in regs: R[n][{(iLo,cLo),(iLo,cHi),(iHi,cLo),(iHi,cHi)}], cLo=n*8+2t
    float R[8][4];
#pragma unroll
    for (int n = 0; n < 8; n++) R[n][0] = R[n][1] = R[n][2] = R[n][3] = 0.f;
    for (int j = 0; j < 32; j++) {
        float w2l = W2[iLo * 32 + j], w2h = W2[iHi * 32 + j];
#pragma unroll
        for (int n = 0; n < 8; n++) {
            float2 hv = *(const float2*)&hT[j * 64 + n * 8 + 2 * t];
            R[n][0] += hv.x * w2l; R[n][1] += hv.y * w2l;
            R[n][2] += hv.x * w2h; R[n][3] += hv.y * w2h;
        }
    }
    {
        float b2l = b2v[iLo], b2h = b2v[iHi];
#pragma unroll
        for (int n = 0; n < 8; n++) {
            R[n][0] += b2l; R[n][1] += b2l; R[n][2] += b2h; R[n][3] += b2h;
        }
    }
    __syncthreads();                 // hT region free (becomes BH)

    auto readout = [&](int ts) {
        float wl = WroS[ts * 256 + iLo], wh = WroS[ts * 256 + iHi];
        float pc[16];
#pragma unroll
        for (int n = 0; n < 8; n++) {
            pc[2 * n]     = R[n][0] * wl + R[n][2] * wh;
            pc[2 * n + 1] = R[n][1] * wl + R[n][3] * wh;
        }
#pragma unroll
        for (int k = 0; k < 16; k++) {
            pc[k] += __shfl_xor_sync(0xFFFFFFFFu, pc[k], 4);
            pc[k] += __shfl_xor_sync(0xFFFFFFFFu, pc[k], 8);
            pc[k] += __shfl_xor_sync(0xFFFFFFFFu, pc[k], 16);
        }
        if (lane < 4) {
#pragma unroll
            for (int n = 0; n < 8; n++) {
                red[w * 64 + n * 8 + 2 * lane]     = pc[2 * n];
                red[w * 64 + n * 8 + 2 * lane + 1] = pc[2 * n + 1];
            }
        }
        __syncthreads();
        if (tid < 64) {
            float a = broS[ts];
#pragma unroll
            for (int ww = 0; ww < 16; ww++) a += red[ww * 64 + tid];
            out[(size_t)(bBase + tid) * 10 + ts] = a;
        }
    };

    // pack fp16 B fragments from fp32 R: layout [q=w][u:4][lane:32][4 u32]
    auto writeB = [&]() {
        u32 vA[16], vB[16];
#pragma unroll
        for (int n = 0; n < 8; n++) {
            u32 Ph01 = pkhf(R[n][0], R[n][1]);
            u32 Ph23 = pkhf(R[n][2], R[n][3]);
            u32 Rh01 = __shfl_xor_sync(0xFFFFFFFFu, Ph01, 4);
            u32 Rh23 = __shfl_xor_sync(0xFFFFFFFFu, Ph23, 4);
            vA[2 * n]     = __byte_perm(Ph01, Rh01, 0x5410);
            vA[2 * n + 1] = __byte_perm(Ph23, Rh23, 0x5410);
            vB[2 * n]     = __byte_perm(Ph01, Rh01, 0x7632);
            vB[2 * n + 1] = __byte_perm(Ph23, Rh23, 0x7632);
        }
        if ((g & 1) == 0) {
            int a  = g >> 1;
            int lA = 8 * t + a, lB = lA + 4;
            uint4* base = (uint4*)(BH + w * 512);
#pragma unroll
            for (int u = 0; u < 4; u++) {
                base[u * 32 + lA] = make_uint4(vA[4*u], vA[4*u+1], vA[4*u+2], vA[4*u+3]);
                base[u * 32 + lB] = make_uint4(vB[4*u], vB[4*u+1], vB[4*u+2], vB[4*u+3]);
            }
        }
    };

    readout(0);
    __syncthreads();
    writeB();

    const uint4* gA4 = (const uint4*)g_A;
    const int aoff = w * 32 + lane;
    const uint4* BH4 = (const uint4*)BH;   // q*128 + u*32 + lane

    float acc[8][4];
#pragma unroll
    for (int n = 0; n < 8; n++) acc[n][0] = acc[n][1] = acc[n][2] = acc[n][3] = 0.f;

    auto domma = [&](const uint4& a,
                     const uint4& b0, const uint4& b1,
                     const uint4& b2, const uint4& b3) {
        mma16816(acc[0], a, b0.x, b0.y); mma16816(acc[1], a, b0.z, b0.w);
        mma16816(acc[2], a, b1.x, b1.y); mma16816(acc[3], a, b1.z, b1.w);
        mma16816(acc[4], a, b2.x, b2.y); mma16816(acc[5], a, b2.z, b2.w);
        mma16816(acc[6], a, b3.x, b3.y); mma16816(acc[7], a, b3.z, b3.w);
    };
    auto epi = [&](int m) {
        float bLo = biasS[m * 256 + iLo], bHi = biasS[m * 256 + iHi];
        if (m == 0) {
#pragma unroll
            for (int n = 0; n < 8; n++) {
                R[n][0] += ftanh(acc[n][0] + bLo);
                R[n][1] += ftanh(acc[n][1] + bLo);
                R[n][2] += ftanh(acc[n][2] + bHi);
                R[n][3] += ftanh(acc[n][3] + bHi);
                acc[n][0] = acc[n][1] = acc[n][2] = acc[n][3] = 0.f;
            }
        } else {
#pragma unroll
            for (int n = 0; n < 8; n++) {
                float2 dw = *(const float2*)&dWs[(m - 1) * 64 + n * 8 + 2 * t];
                R[n][0] += ftanh(acc[n][0] + bLo) * dw.x;
                R[n][1] += ftanh(acc[n][1] + bLo) * dw.y;
                R[n][2] += ftanh(acc[n][2] + bHi) * dw.x;
                R[n][3] += ftanh(acc[n][3] + bHi) * dw.y;
                acc[n][0] = acc[n][1] = acc[n][2] = acc[n][3] = 0.f;
            }
        }
    };

    for (int s = 0; s < 9; s++) {
        {   // dW for this step
            int m = tid >> 6, b = tid & 63;
            const float* ib = inc + (size_t)(bBase + b) * 80;
            dWs[tid] = (s == 0) ? (ib[m] + ib[8 + m]) : ib[(s + 1) * 8 + m];
        }
        __syncthreads();            // dW + B frags visible to all

        const uint4* pab = gA4 + aoff;
        const uint4* bl0 = BH4 + lane;       // q=0
        uint4 a0 = pab[0];
        uint4 c0 = bl0[0], c1 = bl0[32], c2 = bl0[64], c3 = bl0[96];

#pragma unroll 1
        for (int ch = 0; ch < 144; ch += 2) {
            // prefetch chunk ch+1 (A + B frags)
            uint4 a1 = pab[512];
            const uint4* bq1 = BH4 + (((ch + 1) & 15) * 128 + lane);
            uint4 d0 = bq1[0], d1 = bq1[32], d2 = bq1[64], d3 = bq1[96];
            domma(a0, c0, c1, c2, c3);
            // prefetch chunk ch+2 (pad chunks make this always safe)
            a0 = pab[1024];
            const uint4* bq2 = BH4 + (((ch + 2) & 15) * 128 + lane);
            c0 = bq2[0]; c1 = bq2[32]; c2 = bq2[64]; c3 = bq2[96];
            domma(a1, d0, d1, d2, d3);
            if (((ch + 1) & 15) == 15) epi((ch + 1) >> 4);
            pab += 1024;
        }

        readout(s + 1);
        __syncthreads();            // all B-frag reads + red reads done
        if (s < 8) writeB();
    }
}

// ---------------- launch -----------------------------------------------------
extern "C" void kernel_launch(void* const* d_in, const int* in_sizes, int n_in,
                              void* d_out, int out_size) {
    const float* V    = (const float*)d_in[0];
    const float* inc  = (const float*)d_in[1];
    const float* W1   = (const float*)d_in[2];
    const float* b1v  = (const float*)d_in[3];
    const float* W2   = (const float*)d_in[4];
    const float* b2v  = (const float*)d_in[5];
    const float* rho1 = (const float*)d_in[6];
    const float* rho2 = (const float*)d_in[7];
    const float* rho3 = (const float*)d_in[8];
    const float* rho4 = (const float*)d_in[9];
    const float* B1m  = (const float*)d_in[10];
    const float* B2m  = (const float*)d_in[11];
    const float* lam1 = (const float*)d_in[12];
    const float* lam2 = (const float*)d_in[13];
    const float* Wro  = (const float*)d_in[14];
    const float* bro  = (const float*)d_in[15];
    float* out = (float*)d_out;

    const int nB = in_sizes[0] / 16;                  // 16384
    prep_kernel<<<(144 * 16 * 32 * 4 + 255) / 256, 256>>>(B1m, B2m, rho1, rho3);

    cudaFuncSetAttribute(sde_kernel, cudaFuncAttributeMaxDynamicSharedMemorySize, SM_TOT);
    sde_kernel<<<nB / BT, NTH, SM_TOT>>>(V, inc, W1, b1v, W2, b2v,
                                         rho2, rho4, lam1, lam2, Wro, bro, out);
}

// round 16
// speedup vs baseline: 2.7171x; 1.0969x over previous
#include <cuda_runtime.h>
#include <cuda_fp16.h>
#include <cstdint>
typedef unsigned int u32;

#define NTH  256
#define BT   32
// smem byte offsets
#define SO_BH   0          // B fp16 frags [16q][2u][32lane][4u32] 16384
#define SO_BIAS 16384      // 9*256 fp32                            9216
#define SO_WRO  25600      // 10*256 fp32                          10240
#define SO_BRO  35840      // 10 fp32 (pad 64)                        64
#define SO_DW   35904      // 8*32 fp32                             1024
#define SO_RED  36928      // 8*32 fp32                             1024
#define SM_TOT  37952

// A fragments (fp16): [chunk 0..143 (+2 pad)][mtile 16][lane 32][4 u32]
__device__ __align__(256) u32 g_A[146 * 2048];

__device__ __forceinline__ u32 pkhf(float a, float b) {
    __half2 h = __floats2half2_rn(a, b);
    return *(u32*)&h;
}
// fast tanh: (e^2x - 1)/(e^2x + 1), err ~2^-20
__device__ __forceinline__ float ftanh(float x) {
    float e;
    asm("ex2.approx.f32 %0, %1;" : "=f"(e) : "f"(x * 2.885390082f));
    float r;
    asm("rcp.approx.f32 %0, %1;" : "=f"(r) : "f"(e + 1.0f));
    return 1.0f - 2.0f * r;
}
__device__ __forceinline__ void mma16816(float c[4], const uint4& a, u32 b0, u32 b1) {
    asm volatile("mma.sync.aligned.m16n8k16.row.col.f32.f16.f16.f32 "
        "{%0,%1,%2,%3}, {%4,%5,%6,%7}, {%8,%9}, {%0,%1,%2,%3};"
        : "+f"(c[0]), "+f"(c[1]), "+f"(c[2]), "+f"(c[3])
        : "r"(a.x), "r"(a.y), "r"(a.z), "r"(a.w), "r"(b0), "r"(b1));
}

// ---------------- prep: rho-fold + fp16 + fragment layout (unchanged) -------
__global__ void prep_kernel(const float* __restrict__ B1m, const float* __restrict__ B2m,
                            const float* __restrict__ r1, const float* __restrict__ r3) {
    int idx = blockIdx.x * 256 + threadIdx.x;
    if (idx >= 144 * 16 * 32 * 4) return;
    int r = idx & 3, l = (idx >> 2) & 31, mt = (idx >> 7) & 15, ch = idx >> 11;
    int m = ch >> 4, q = ch & 15;
    int gg = l >> 2, tt = l & 3;
    int i = mt * 16 + gg + ((r & 1) ? 8 : 0);
    int k = q * 16 + 2 * tt + ((r & 2) ? 8 : 0);
    float rho = (m == 0) ? r1[0] : r3[0];
    const float* Bs = (m == 0) ? (B1m + i * 256) : (B2m + (m - 1) * 65536 + i * 256);
    g_A[ch * 2048 + mt * 128 + l * 4 + r] = pkhf(rho * Bs[k], rho * Bs[k + 1]);
}

// ---------------- main kernel ------------------------------------------------
__global__ __launch_bounds__(NTH, 2)
void sde_kernel(const float* __restrict__ V, const float* __restrict__ inc,
                const float* __restrict__ W1, const float* __restrict__ b1v,
                const float* __restrict__ W2, const float* __restrict__ b2v,
                const float* __restrict__ rho2, const float* __restrict__ rho4,
                const float* __restrict__ lam1, const float* __restrict__ lam2,
                const float* __restrict__ Wro,  const float* __restrict__ bro,
                float* __restrict__ out) {
    extern __shared__ __align__(16) char sm[];
    u32*   BH    = (u32*)(sm + SO_BH);
    float* biasS = (float*)(sm + SO_BIAS);
    float* WroS  = (float*)(sm + SO_WRO);
    float* broS  = (float*)(sm + SO_BRO);
    float* dWs   = (float*)(sm + SO_DW);
    float* red   = (float*)(sm + SO_RED);

    const int tid = threadIdx.x, lane = tid & 31, w = tid >> 5;   // w: 0..7
    const int g = lane >> 2, t = lane & 3;
    const int bBase = blockIdx.x * BT;
    // warp w owns mtiles {2w, 2w+1}: rows w*32+mt*16+{g, g+8}, cols 0..31
    const int iLo0 = w * 32 + g, iLo1 = iLo0 + 16;

    // prologue: biases (rho folded), readout weights
    {
        float r2 = rho2[0], r4 = rho4[0];
        for (int e = tid; e < 2304; e += NTH) {
            int m = e >> 8, i = e & 255;
            biasS[e] = (m == 0) ? r2 * lam1[i] : r4 * lam2[(m - 1) * 256 + i];
        }
        for (int e = tid; e < 2560; e += NTH) WroS[e] = Wro[e];
        if (tid < 10) broS[tid] = bro[tid];
    }
    // hT[j][b] = tanh(V W1^T + b1), staged in BH region
    float* hT = (float*)(sm + SO_BH);
    for (int e = tid; e < 1024; e += NTH) {
        int j = e & 31, b = e >> 5;
        const float* vb = V + (size_t)(bBase + b) * 16;
        const float* ww = W1 + j * 16;
        float s = b1v[j];
#pragma unroll
        for (int u = 0; u < 16; u++) s += vb[u] * ww[u];
        hT[j * 32 + b] = ftanh(s);
    }
    __syncthreads();

    // R0 in regs: R[mt][n][{(iLo,c0),(iLo,c1),(iHi,c0),(iHi,c1)}], c0=n*8+2t
    float R[2][4][4];
#pragma unroll
    for (int mt = 0; mt < 2; mt++)
#pragma unroll
        for (int n = 0; n < 4; n++)
            R[mt][n][0] = R[mt][n][1] = R[mt][n][2] = R[mt][n][3] = 0.f;
    for (int j = 0; j < 32; j++) {
        float wl0 = W2[iLo0 * 32 + j], wh0 = W2[(iLo0 + 8) * 32 + j];
        float wl1 = W2[iLo1 * 32 + j], wh1 = W2[(iLo1 + 8) * 32 + j];
#pragma unroll
        for (int n = 0; n < 4; n++) {
            float2 hv = *(const float2*)&hT[j * 32 + n * 8 + 2 * t];
            R[0][n][0] += hv.x * wl0; R[0][n][1] += hv.y * wl0;
            R[0][n][2] += hv.x * wh0; R[0][n][3] += hv.y * wh0;
            R[1][n][0] += hv.x * wl1; R[1][n][1] += hv.y * wl1;
            R[1][n][2] += hv.x * wh1; R[1][n][3] += hv.y * wh1;
        }
    }
    {
        float b0 = b2v[iLo0], b1 = b2v[iLo0 + 8];
        float b2 = b2v[iLo1], b3 = b2v[iLo1 + 8];
#pragma unroll
        for (int n = 0; n < 4; n++) {
            R[0][n][0] += b0; R[0][n][1] += b0; R[0][n][2] += b1; R[0][n][3] += b1;
            R[1][n][0] += b2; R[1][n][1] += b2; R[1][n][2] += b3; R[1][n][3] += b3;
        }
    }
    __syncthreads();                 // hT region free (becomes BH)

    auto readout = [&](int ts) {
        float wl0 = WroS[ts * 256 + iLo0], wh0 = WroS[ts * 256 + iLo0 + 8];
        float wl1 = WroS[ts * 256 + iLo1], wh1 = WroS[ts * 256 + iLo1 + 8];
        float pc[8];
#pragma unroll
        for (int n = 0; n < 4; n++) {
            pc[2 * n]     = R[0][n][0] * wl0 + R[0][n][2] * wh0
                          + R[1][n][0] * wl1 + R[1][n][2] * wh1;
            pc[2 * n + 1] = R[0][n][1] * wl0 + R[0][n][3] * wh0
                          + R[1][n][1] * wl1 + R[1][n][3] * wh1;
        }
#pragma unroll
        for (int k = 0; k < 8; k++) {
            pc[k] += __shfl_xor_sync(0xFFFFFFFFu, pc[k], 4);
            pc[k] += __shfl_xor_sync(0xFFFFFFFFu, pc[k], 8);
            pc[k] += __shfl_xor_sync(0xFFFFFFFFu, pc[k], 16);
        }
        if (g == 0) {
#pragma unroll
            for (int n = 0; n < 4; n++) {
                red[w * 32 + n * 8 + 2 * t]     = pc[2 * n];
                red[w * 32 + n * 8 + 2 * t + 1] = pc[2 * n + 1];
            }
        }
        __syncthreads();
        if (tid < 32) {
            float a = broS[ts];
#pragma unroll
            for (int ww = 0; ww < 8; ww++) a += red[ww * 32 + tid];
            out[(size_t)(bBase + tid) * 10 + ts] = a;
        }
    };

    // pack fp16 B fragments: layout [q:16][u:2][lane:32][4 u32]; q = 2w+mt
    auto writeB = [&]() {
#pragma unroll
        for (int mt = 0; mt < 2; mt++) {
            u32 vA[8], vB[8];
#pragma unroll
            for (int n = 0; n < 4; n++) {
                u32 Ph01 = pkhf(R[mt][n][0], R[mt][n][1]);
                u32 Ph23 = pkhf(R[mt][n][2], R[mt][n][3]);
                u32 Rh01 = __shfl_xor_sync(0xFFFFFFFFu, Ph01, 4);
                u32 Rh23 = __shfl_xor_sync(0xFFFFFFFFu, Ph23, 4);
                vA[2 * n]     = __byte_perm(Ph01, Rh01, 0x5410);
                vA[2 * n + 1] = __byte_perm(Ph23, Rh23, 0x5410);
                vB[2 * n]     = __byte_perm(Ph01, Rh01, 0x7632);
                vB[2 * n + 1] = __byte_perm(Ph23, Rh23, 0x7632);
            }
            if ((g & 1) == 0) {
                int a  = g >> 1;
                int lA = 8 * t + a, lB = lA + 4;
                uint4* bq = (uint4*)(BH + (2 * w + mt) * 256);
#pragma unroll
                for (int u = 0; u < 2; u++) {
                    bq[u * 32 + lA] = make_uint4(vA[4*u], vA[4*u+1], vA[4*u+2], vA[4*u+3]);
                    bq[u * 32 + lB] = make_uint4(vB[4*u], vB[4*u+1], vB[4*u+2], vB[4*u+3]);
                }
            }
        }
    };

    readout(0);
    __syncthreads();
    writeB();

    const uint4* gA4 = (const uint4*)g_A;
    const int aoff = w * 64 + lane;        // mtile 2w; mtile 2w+1 at +32
    const uint4* BH4 = (const uint4*)BH;   // q*64 + u*32 + lane

    float acc[2][4][4];
#pragma unroll
    for (int mt = 0; mt < 2; mt++)
#pragma unroll
        for (int n = 0; n < 4; n++)
            acc[mt][n][0] = acc[mt][n][1] = acc[mt][n][2] = acc[mt][n][3] = 0.f;

    auto domma = [&](const uint4& a0, const uint4& a1,
                     const uint4& b0, const uint4& b1) {
        mma16816(acc[0][0], a0, b0.x, b0.y); mma16816(acc[0][1], a0, b0.z, b0.w);
        mma16816(acc[0][2], a0, b1.x, b1.y); mma16816(acc[0][3], a0, b1.z, b1.w);
        mma16816(acc[1][0], a1, b0.x, b0.y); mma16816(acc[1][1], a1, b0.z, b0.w);
        mma16816(acc[1][2], a1, b1.x, b1.y); mma16816(acc[1][3], a1, b1.z, b1.w);
    };
    auto epi = [&](int m) {
        const float* bm = biasS + m * 256;
        float bL0 = bm[iLo0], bH0 = bm[iLo0 + 8];
        float bL1 = bm[iLo1], bH1 = bm[iLo1 + 8];
        if (m == 0) {
#pragma unroll
            for (int n = 0; n < 4; n++) {
                R[0][n][0] += ftanh(acc[0][n][0] + bL0);
                R[0][n][1] += ftanh(acc[0][n][1] + bL0);
                R[0][n][2] += ftanh(acc[0][n][2] + bH0);
                R[0][n][3] += ftanh(acc[0][n][3] + bH0);
                R[1][n][0] += ftanh(acc[1][n][0] + bL1);
                R[1][n][1] += ftanh(acc[1][n][1] + bL1);
                R[1][n][2] += ftanh(acc[1][n][2] + bH1);
                R[1][n][3] += ftanh(acc[1][n][3] + bH1);
#pragma unroll
                for (int mt = 0; mt < 2; mt++)
                    acc[mt][n][0] = acc[mt][n][1] = acc[mt][n][2] = acc[mt][n][3] = 0.f;
            }
        } else {
#pragma unroll
            for (int n = 0; n < 4; n++) {
                float2 dw = *(const float2*)&dWs[(m - 1) * 32 + n * 8 + 2 * t];
                R[0][n][0] += ftanh(acc[0][n][0] + bL0) * dw.x;
                R[0][n][1] += ftanh(acc[0][n][1] + bL0) * dw.y;
                R[0][n][2] += ftanh(acc[0][n][2] + bH0) * dw.x;
                R[0][n][3] += ftanh(acc[0][n][3] + bH0) * dw.y;
                R[1][n][0] += ftanh(acc[1][n][0] + bL1) * dw.x;
                R[1][n][1] += ftanh(acc[1][n][1] + bL1) * dw.y;
                R[1][n][2] += ftanh(acc[1][n][2] + bH1) * dw.x;
                R[1][n][3] += ftanh(acc[1][n][3] + bH1) * dw.y;
#pragma unroll
                for (int mt = 0; mt < 2; mt++)
                    acc[mt][n][0] = acc[mt][n][1] = acc[mt][n][2] = acc[mt][n][3] = 0.f;
            }
        }
    };

    for (int s = 0; s < 9; s++) {
        {   // dW for this step: tid = m*32 + b (256 = 8*32)
            int m = tid >> 5, b = tid & 31;
            const float* ib = inc + (size_t)(bBase + b) * 80;
            dWs[tid] = (s == 0) ? (ib[m] + ib[8 + m]) : ib[(s + 1) * 8 + m];
        }
        __syncthreads();            // dW + B frags visible to all

        const uint4* pab = gA4 + aoff;
        const uint4* bl0 = BH4 + lane;       // q=0
        uint4 a00 = pab[0], a01 = pab[32];
        uint4 c0 = bl0[0], c1 = bl0[32];

#pragma unroll 1
        for (int ch = 0; ch < 144; ch += 2) {
            // prefetch chunk ch+1 (A + B frags)
            uint4 a10 = pab[512], a11 = pab[544];
            const uint4* bq1 = BH4 + (((ch + 1) & 15) * 64 + lane);
            uint4 d0 = bq1[0], d1 = bq1[32];
            domma(a00, a01, c0, c1);
            // prefetch chunk ch+2 (pad chunks make this always safe)
            a00 = pab[1024]; a01 = pab[1056];
            const uint4* bq2 = BH4 + (((ch + 2) & 15) * 64 + lane);
            c0 = bq2[0]; c1 = bq2[32];
            domma(a10, a11, d0, d1);
            if (((ch + 1) & 15) == 15) epi((ch + 1) >> 4);
            pab += 1024;
        }

        readout(s + 1);
        __syncthreads();            // all B-frag reads + red reads done
        if (s < 8) writeB();
    }
}

// ---------------- launch -----------------------------------------------------
extern "C" void kernel_launch(void* const* d_in, const int* in_sizes, int n_in,
                              void* d_out, int out_size) {
    const float* V    = (const float*)d_in[0];
    const float* inc  = (const float*)d_in[1];
    const float* W1   = (const float*)d_in[2];
    const float* b1v  = (const float*)d_in[3];
    const float* W2   = (const float*)d_in[4];
    const float* b2v  = (const float*)d_in[5];
    const float* rho1 = (const float*)d_in[6];
    const float* rho2 = (const float*)d_in[7];
    const float* rho3 = (const float*)d_in[8];
    const float* rho4 = (const float*)d_in[9];
    const float* B1m  = (const float*)d_in[10];
    const float* B2m  = (const float*)d_in[11];
    const float* lam1 = (const float*)d_in[12];
    const float* lam2 = (const float*)d_in[13];
    const float* Wro  = (const float*)d_in[14];
    const float* bro  = (const float*)d_in[15];
    float* out = (float*)d_out;

    const int nB = in_sizes[0] / 16;                  // 16384
    prep_kernel<<<(144 * 16 * 32 * 4 + 255) / 256, 256>>>(B1m, B2m, rho1, rho3);

    cudaFuncSetAttribute(sde_kernel, cudaFuncAttributeMaxDynamicSharedMemorySize, SM_TOT);
    sde_kernel<<<nB / BT, NTH, SM_TOT>>>(V, inc, W1, b1v, W2, b2v,
                                         rho2, rho4, lam1, lam2, Wro, bro, out);
}

// round 17
// speedup vs baseline: 2.7189x; 1.0007x over previous
#include <cuda_runtime.h>
#include <cuda_fp16.h>
#include <cstdint>
typedef unsigned int u32;

#define NTH  256
#define BT   32
// smem byte offsets
#define SO_BH   0          // B fp16 frags [16q][2u][32lane][4u32] 16384
#define SO_BIAS 16384      // 9*256 fp32                            9216
#define SO_WRO  25600      // 10*256 fp32                          10240
#define SO_BRO  35840      // 10 fp32 (pad 64)                        64
#define SO_DW   35904      // 8*32 fp32                             1024
#define SO_RED  36928      // 8*32 fp32                             1024
#define SM_TOT  37952

// A fragments (fp16): [chunk 0..143 (+2 pad)][mtile 16][lane 32][4 u32]
__device__ __align__(256) u32 g_A[146 * 2048];

__device__ __forceinline__ u32 pkhf(float a, float b) {
    __half2 h = __floats2half2_rn(a, b);
    return *(u32*)&h;
}
// fast tanh: (e^2x - 1)/(e^2x + 1), err ~2^-20
__device__ __forceinline__ float ftanh(float x) {
    float e;
    asm("ex2.approx.f32 %0, %1;" : "=f"(e) : "f"(x * 2.885390082f));
    float r;
    asm("rcp.approx.f32 %0, %1;" : "=f"(r) : "f"(e + 1.0f));
    return 1.0f - 2.0f * r;
}
__device__ __forceinline__ void mma16816(float c[4], const uint4& a, u32 b0, u32 b1) {
    asm volatile("mma.sync.aligned.m16n8k16.row.col.f32.f16.f16.f32 "
        "{%0,%1,%2,%3}, {%4,%5,%6,%7}, {%8,%9}, {%0,%1,%2,%3};"
        : "+f"(c[0]), "+f"(c[1]), "+f"(c[2]), "+f"(c[3])
        : "r"(a.x), "r"(a.y), "r"(a.z), "r"(a.w), "r"(b0), "r"(b1));
}

// ---------------- prep: rho-fold + fp16 + fragment layout (unchanged) -------
__global__ void prep_kernel(const float* __restrict__ B1m, const float* __restrict__ B2m,
                            const float* __restrict__ r1, const float* __restrict__ r3) {
    int idx = blockIdx.x * 256 + threadIdx.x;
    if (idx >= 144 * 16 * 32 * 4) return;
    int r = idx & 3, l = (idx >> 2) & 31, mt = (idx >> 7) & 15, ch = idx >> 11;
    int m = ch >> 4, q = ch & 15;
    int gg = l >> 2, tt = l & 3;
    int i = mt * 16 + gg + ((r & 1) ? 8 : 0);
    int k = q * 16 + 2 * tt + ((r & 2) ? 8 : 0);
    float rho = (m == 0) ? r1[0] : r3[0];
    const float* Bs = (m == 0) ? (B1m + i * 256) : (B2m + (m - 1) * 65536 + i * 256);
    g_A[ch * 2048 + mt * 128 + l * 4 + r] = pkhf(rho * Bs[k], rho * Bs[k + 1]);
}

// ---------------- main kernel ------------------------------------------------
__global__ __launch_bounds__(NTH, 2)
void sde_kernel(const float* __restrict__ V, const float* __restrict__ inc,
                const float* __restrict__ W1, const float* __restrict__ b1v,
                const float* __restrict__ W2, const float* __restrict__ b2v,
                const float* __restrict__ rho2, const float* __restrict__ rho4,
                const float* __restrict__ lam1, const float* __restrict__ lam2,
                const float* __restrict__ Wro,  const float* __restrict__ bro,
                float* __restrict__ out) {
    extern __shared__ __align__(16) char sm[];
    u32*   BH    = (u32*)(sm + SO_BH);
    float* biasS = (float*)(sm + SO_BIAS);
    float* WroS  = (float*)(sm + SO_WRO);
    float* broS  = (float*)(sm + SO_BRO);
    float* dWs   = (float*)(sm + SO_DW);
    float* red   = (float*)(sm + SO_RED);

    const int tid = threadIdx.x, lane = tid & 31, w = tid >> 5;   // w: 0..7
    const int g = lane >> 2, t = lane & 3;
    const int bBase = blockIdx.x * BT;
    // warp w owns mtiles {2w, 2w+1}: rows w*32+mt*16+{g, g+8}, cols 0..31
    const int iLo0 = w * 32 + g, iLo1 = iLo0 + 16;

    // prologue: biases (rho folded), readout weights
    {
        float r2 = rho2[0], r4 = rho4[0];
        for (int e = tid; e < 2304; e += NTH) {
            int m = e >> 8, i = e & 255;
            biasS[e] = (m == 0) ? r2 * lam1[i] : r4 * lam2[(m - 1) * 256 + i];
        }
        for (int e = tid; e < 2560; e += NTH) WroS[e] = Wro[e];
        if (tid < 10) broS[tid] = bro[tid];
    }
    // hT[j][b] = tanh(V W1^T + b1), staged in BH region
    float* hT = (float*)(sm + SO_BH);
    for (int e = tid; e < 1024; e += NTH) {
        int j = e & 31, b = e >> 5;
        const float* vb = V + (size_t)(bBase + b) * 16;
        const float* ww = W1 + j * 16;
        float s = b1v[j];
#pragma unroll
        for (int u = 0; u < 16; u++) s += vb[u] * ww[u];
        hT[j * 32 + b] = ftanh(s);
    }
    __syncthreads();

    // R0 in regs: R[mt][n][{(iLo,c0),(iLo,c1),(iHi,c0),(iHi,c1)}], c0=n*8+2t
    float R[2][4][4];
#pragma unroll
    for (int mt = 0; mt < 2; mt++)
#pragma unroll
        for (int n = 0; n < 4; n++)
            R[mt][n][0] = R[mt][n][1] = R[mt][n][2] = R[mt][n][3] = 0.f;
    for (int j = 0; j < 32; j++) {
        float wl0 = W2[iLo0 * 32 + j], wh0 = W2[(iLo0 + 8) * 32 + j];
        float wl1 = W2[iLo1 * 32 + j], wh1 = W2[(iLo1 + 8) * 32 + j];
#pragma unroll
        for (int n = 0; n < 4; n++) {
            float2 hv = *(const float2*)&hT[j * 32 + n * 8 + 2 * t];
            R[0][n][0] += hv.x * wl0; R[0][n][1] += hv.y * wl0;
            R[0][n][2] += hv.x * wh0; R[0][n][3] += hv.y * wh0;
            R[1][n][0] += hv.x * wl1; R[1][n][1] += hv.y * wl1;
            R[1][n][2] += hv.x * wh1; R[1][n][3] += hv.y * wh1;
        }
    }
    {
        float b0 = b2v[iLo0], b1 = b2v[iLo0 + 8];
        float b2 = b2v[iLo1], b3 = b2v[iLo1 + 8];
#pragma unroll
        for (int n = 0; n < 4; n++) {
            R[0][n][0] += b0; R[0][n][1] += b0; R[0][n][2] += b1; R[0][n][3] += b1;
            R[1][n][0] += b2; R[1][n][1] += b2; R[1][n][2] += b3; R[1][n][3] += b3;
        }
    }
    __syncthreads();                 // hT region free (becomes BH)

    auto readout = [&](int ts) {
        float wl0 = WroS[ts * 256 + iLo0], wh0 = WroS[ts * 256 + iLo0 + 8];
        float wl1 = WroS[ts * 256 + iLo1], wh1 = WroS[ts * 256 + iLo1 + 8];
        float pc[8];
#pragma unroll
        for (int n = 0; n < 4; n++) {
            pc[2 * n]     = R[0][n][0] * wl0 + R[0][n][2] * wh0
                          + R[1][n][0] * wl1 + R[1][n][2] * wh1;
            pc[2 * n + 1] = R[0][n][1] * wl0 + R[0][n][3] * wh0
                          + R[1][n][1] * wl1 + R[1][n][3] * wh1;
        }
#pragma unroll
        for (int k = 0; k < 8; k++) {
            pc[k] += __shfl_xor_sync(0xFFFFFFFFu, pc[k], 4);
            pc[k] += __shfl_xor_sync(0xFFFFFFFFu, pc[k], 8);
            pc[k] += __shfl_xor_sync(0xFFFFFFFFu, pc[k], 16);
        }
        if (g == 0) {
#pragma unroll
            for (int n = 0; n < 4; n++) {
                red[w * 32 + n * 8 + 2 * t]     = pc[2 * n];
                red[w * 32 + n * 8 + 2 * t + 1] = pc[2 * n + 1];
            }
        }
        __syncthreads();
        if (tid < 32) {
            float a = broS[ts];
#pragma unroll
            for (int ww = 0; ww < 8; ww++) a += red[ww * 32 + tid];
            out[(size_t)(bBase + tid) * 10 + ts] = a;
        }
    };

    // pack fp16 B fragments: layout [q:16][u:2][lane:32][4 u32]; q = 2w+mt
    auto writeB = [&]() {
#pragma unroll
        for (int mt = 0; mt < 2; mt++) {
            u32 vA[8], vB[8];
#pragma unroll
            for (int n = 0; n < 4; n++) {
                u32 Ph01 = pkhf(R[mt][n][0], R[mt][n][1]);
                u32 Ph23 = pkhf(R[mt][n][2], R[mt][n][3]);
                u32 Rh01 = __shfl_xor_sync(0xFFFFFFFFu, Ph01, 4);
                u32 Rh23 = __shfl_xor_sync(0xFFFFFFFFu, Ph23, 4);
                vA[2 * n]     = __byte_perm(Ph01, Rh01, 0x5410);
                vA[2 * n + 1] = __byte_perm(Ph23, Rh23, 0x5410);
                vB[2 * n]     = __byte_perm(Ph01, Rh01, 0x7632);
                vB[2 * n + 1] = __byte_perm(Ph23, Rh23, 0x7632);
            }
            if ((g & 1) == 0) {
                int a  = g >> 1;
                int lA = 8 * t + a, lB = lA + 4;
                uint4* bq = (uint4*)(BH + (2 * w + mt) * 256);
#pragma unroll
                for (int u = 0; u < 2; u++) {
                    bq[u * 32 + lA] = make_uint4(vA[4*u], vA[4*u+1], vA[4*u+2], vA[4*u+3]);
                    bq[u * 32 + lB] = make_uint4(vB[4*u], vB[4*u+1], vB[4*u+2], vB[4*u+3]);
                }
            }
        }
    };

    readout(0);
    __syncthreads();
    writeB();

    const uint4* gA4 = (const uint4*)g_A;
    const int aoff = w * 64 + lane;        // mtile 2w; mtile 2w+1 at +32
    const uint4* BH4 = (const uint4*)BH;   // q*64 + u*32 + lane

    float acc[2][4][4];
#pragma unroll
    for (int mt = 0; mt < 2; mt++)
#pragma unroll
        for (int n = 0; n < 4; n++)
            acc[mt][n][0] = acc[mt][n][1] = acc[mt][n][2] = acc[mt][n][3] = 0.f;

    auto domma = [&](const uint4& a0, const uint4& a1,
                     const uint4& b0, const uint4& b1) {
        mma16816(acc[0][0], a0, b0.x, b0.y); mma16816(acc[0][1], a0, b0.z, b0.w);
        mma16816(acc[0][2], a0, b1.x, b1.y); mma16816(acc[0][3], a0, b1.z, b1.w);
        mma16816(acc[1][0], a1, b0.x, b0.y); mma16816(acc[1][1], a1, b0.z, b0.w);
        mma16816(acc[1][2], a1, b1.x, b1.y); mma16816(acc[1][3], a1, b1.z, b1.w);
    };
    auto epi = [&](int m) {
        const float* bm = biasS + m * 256;
        float bL0 = bm[iLo0], bH0 = bm[iLo0 + 8];
        float bL1 = bm[iLo1], bH1 = bm[iLo1 + 8];
        if (m == 0) {
#pragma unroll
            for (int n = 0; n < 4; n++) {
                R[0][n][0] += ftanh(acc[0][n][0] + bL0);
                R[0][n][1] += ftanh(acc[0][n][1] + bL0);
                R[0][n][2] += ftanh(acc[0][n][2] + bH0);
                R[0][n][3] += ftanh(acc[0][n][3] + bH0);
                R[1][n][0] += ftanh(acc[1][n][0] + bL1);
                R[1][n][1] += ftanh(acc[1][n][1] + bL1);
                R[1][n][2] += ftanh(acc[1][n][2] + bH1);
                R[1][n][3] += ftanh(acc[1][n][3] + bH1);
#pragma unroll
                for (int mt = 0; mt < 2; mt++)
                    acc[mt][n][0] = acc[mt][n][1] = acc[mt][n][2] = acc[mt][n][3] = 0.f;
            }
        } else {
#pragma unroll
            for (int n = 0; n < 4; n++) {
                float2 dw = *(const float2*)&dWs[(m - 1) * 32 + n * 8 + 2 * t];
                R[0][n][0] += ftanh(acc[0][n][0] + bL0) * dw.x;
                R[0][n][1] += ftanh(acc[0][n][1] + bL0) * dw.y;
                R[0][n][2] += ftanh(acc[0][n][2] + bH0) * dw.x;
                R[0][n][3] += ftanh(acc[0][n][3] + bH0) * dw.y;
                R[1][n][0] += ftanh(acc[1][n][0] + bL1) * dw.x;
                R[1][n][1] += ftanh(acc[1][n][1] + bL1) * dw.y;
                R[1][n][2] += ftanh(acc[1][n][2] + bH1) * dw.x;
                R[1][n][3] += ftanh(acc[1][n][3] + bH1) * dw.y;
#pragma unroll
                for (int mt = 0; mt < 2; mt++)
                    acc[mt][n][0] = acc[mt][n][1] = acc[mt][n][2] = acc[mt][n][3] = 0.f;
            }
        }
    };

    for (int s = 0; s < 9; s++) {
        {   // dW for this step: tid = m*32 + b (256 = 8*32)
            int m = tid >> 5, b = tid & 31;
            const float* ib = inc + (size_t)(bBase + b) * 80;
            dWs[tid] = (s == 0) ? (ib[m] + ib[8 + m]) : ib[(s + 1) * 8 + m];
        }
        __syncthreads();            // dW + B frags visible to all

        const uint4* pab = gA4 + aoff;
        const uint4* bl0 = BH4 + lane;       // q=0
        uint4 a00 = pab[0], a01 = pab[32];
        uint4 c0 = bl0[0], c1 = bl0[32];

#pragma unroll 1
        for (int ch = 0; ch < 144; ch += 2) {
            // prefetch chunk ch+1 (A + B frags)
            uint4 a10 = pab[512], a11 = pab[544];
            const uint4* bq1 = BH4 + (((ch + 1) & 15) * 64 + lane);
            uint4 d0 = bq1[0], d1 = bq1[32];
            domma(a00, a01, c0, c1);
            // prefetch chunk ch+2 (pad chunks make this always safe)
            a00 = pab[1024]; a01 = pab[1056];
            const uint4* bq2 = BH4 + (((ch + 2) & 15) * 64 + lane);
            c0 = bq2[0]; c1 = bq2[32];
            domma(a10, a11, d0, d1);
            if (((ch + 1) & 15) == 15) epi((ch + 1) >> 4);
            pab += 1024;
        }

        readout(s + 1);
        __syncthreads();            // all B-frag reads + red reads done
        if (s < 8) writeB();
    }
}

// ---------------- launch -----------------------------------------------------
extern "C" void kernel_launch(void* const* d_in, const int* in_sizes, int n_in,
                              void* d_out, int out_size) {
    const float* V    = (const float*)d_in[0];
    const float* inc  = (const float*)d_in[1];
    const float* W1   = (const float*)d_in[2];
    const float* b1v  = (const float*)d_in[3];
    const float* W2   = (const float*)d_in[4];
    const float* b2v  = (const float*)d_in[5];
    const float* rho1 = (const float*)d_in[6];
    const float* rho2 = (const float*)d_in[7];
    const float* rho3 = (const float*)d_in[8];
    const float* rho4 = (const float*)d_in[9];
    const float* B1m  = (const float*)d_in[10];
    const float* B2m  = (const float*)d_in[11];
    const float* lam1 = (const float*)d_in[12];
    const float* lam2 = (const float*)d_in[13];
    const float* Wro  = (const float*)d_in[14];
    const float* bro  = (const float*)d_in[15];
    float* out = (float*)d_out;

    const int nB = in_sizes[0] / 16;                  // 16384
    prep_kernel<<<(144 * 16 * 32 * 4 + 255) / 256, 256>>>(B1m, B2m, rho1, rho3);

    cudaFuncSetAttribute(sde_kernel, cudaFuncAttributeMaxDynamicSharedMemorySize, SM_TOT);
    sde_kernel<<<nB / BT, NTH, SM_TOT>>>(V, inc, W1, b1v, W2, b2v,
                                         rho2, rho4, lam1, lam2, Wro, bro, out);
}